// round 11
// baseline (speedup 1.0000x reference)
#include <cuda_runtime.h>

#define N_QUBITS 10
#define TPB 128

// Closed-form evaluation of the 10-qubit staircase circuit:
//   E_0 = cos(x_0 + r_0)
//   E_i = cos(x_i + r_i) * ((1-k_{i-1}) + k_{i-1} * E_{i-1}),  k_j = (1 - cos e_j)/2
// (R0 derivation: each entangling gate is diagonal in its control qubit's Z
// basis; only the diagonal of the 2x2 reduced density matrix propagates,
// collapsing the 2^10 state vector to a 10-step scalar recurrence.)
//
// One sample per thread (16384 threads = 128 CTAs x 128: the measured-best
// parallelism). Parameter processing (k = sin^2(e/2), kc = 1-k, r copy) is
// done once per CTA by warp 0 and broadcast via shared memory, cutting ~35
// redundant issued instructions from every thread. Data loads are issued
// before the barrier so DRAM latency overlaps the barrier wait.
__global__ void __launch_bounds__(TPB, 1)
qsa_closed_form_kernel(const float2* __restrict__ inputs2,
                       const float* __restrict__ rot,
                       const float* __restrict__ ent,
                       float2* __restrict__ out2) {
    __shared__ float s_r[N_QUBITS];
    __shared__ float s_k[N_QUBITS - 1];
    __shared__ float s_kc[N_QUBITS - 1];

    const int t = blockIdx.x * TPB + threadIdx.x;   // sample index, exact fit

    // 5 independent LDG.64 (MLP = 5), issued before the barrier.
    float2 v[5];
    const float2* src = inputs2 + t * 5;
    #pragma unroll
    for (int i = 0; i < 5; i++) v[i] = src[i];

    // Warp 0: one lane per parameter. Coalesced single-request loads.
    if (threadIdx.x < 32) {
        int lane = threadIdx.x;
        if (lane < N_QUBITS) s_r[lane] = __ldg(&rot[lane]);
        if (lane < N_QUBITS - 1) {
            float kk = 0.5f - 0.5f * __cosf(__ldg(&ent[lane]));  // sin^2(e/2)
            s_k[lane]  = kk;
            s_kc[lane] = 1.0f - kk;
        }
    }
    __syncthreads();

    float x[N_QUBITS];
    #pragma unroll
    for (int i = 0; i < 5; i++) { x[2*i] = v[i].x; x[2*i+1] = v[i].y; }

    // Broadcast LDS reads (compile-time offsets -> vectorized, conflict-free).
    float r[N_QUBITS], k[N_QUBITS - 1], kc[N_QUBITS - 1];
    #pragma unroll
    for (int i = 0; i < N_QUBITS; i++) r[i] = s_r[i];
    #pragma unroll
    for (int i = 0; i < N_QUBITS - 1; i++) { k[i] = s_k[i]; kc[i] = s_kc[i]; }

    // All 10 cos independent (pipelined MUFU); carry chain mul+fma per step.
    float c[N_QUBITS];
    #pragma unroll
    for (int i = 0; i < N_QUBITS; i++) c[i] = __cosf(x[i] + r[i]);

    float e[N_QUBITS];
    float carry = 1.0f;
    #pragma unroll
    for (int i = 0; i < N_QUBITS; i++) {
        float ev = c[i] * carry;
        e[i] = ev;
        if (i < N_QUBITS - 1) carry = __fmaf_rn(k[i], ev, kc[i]);
    }

    float2* dst = out2 + t * 5;
    #pragma unroll
    for (int i = 0; i < 5; i++) {
        float2 o; o.x = e[2*i]; o.y = e[2*i+1];
        dst[i] = o;
    }
}

extern "C" void kernel_launch(void* const* d_in, const int* in_sizes, int n_in,
                              void* d_out, int out_size) {
    const float* inputs = (const float*)d_in[0];  // (16, 1024, 10) fp32
    const float* rot    = (const float*)d_in[1];  // (10,)
    const float* ent    = (const float*)d_in[2];  // (9,)
    float* out = (float*)d_out;

    int total_elems = in_sizes[0];                 // 163840
    int T = total_elems / N_QUBITS;                // 16384 samples
    int blocks = T / TPB;                          // 128, exact

    qsa_closed_form_kernel<<<blocks, TPB>>>(
        reinterpret_cast<const float2*>(inputs), rot, ent,
        reinterpret_cast<float2*>(out));
}

// round 12
// speedup vs baseline: 1.2452x; 1.2452x over previous
#include <cuda_runtime.h>

#define N_QUBITS 10
#define TPB 128

// Closed-form evaluation of the 10-qubit staircase circuit:
//   E_0 = cos(x_0 + r_0)
//   E_i = cos(x_i + r_i) * ((1-k_{i-1}) + k_{i-1} * E_{i-1}),  k_j = (1 - cos e_j)/2
// (R0 derivation: each entangling gate is diagonal in its control qubit's Z
// basis; only the diagonal of the 2x2 reduced density matrix propagates,
// collapsing the 2^10 state vector to a 10-step scalar recurrence.)
//
// R9 structure restored (best measured: 6.144us): one sample per thread,
// 16384 threads = 128 CTAs x 128, single wave, no smem, no barriers,
// vectorized parameter loads (5 LDGs instead of 19). R10/R11 proved that
// trading parallelism (SPT=2) or adding a barrier (smem param broadcast)
// regresses the timed loop. This round: k/kc each computed as ONE FMA off
// the shared MUFU cos result (k = fma(-.5,c,.5), kc = fma(.5,c,.5)).
__global__ void __launch_bounds__(TPB, 1)
qsa_closed_form_kernel(const float2* __restrict__ inputs2,
                       const float* __restrict__ rot,
                       const float* __restrict__ ent,
                       float2* __restrict__ out2) {
    const int t = blockIdx.x * TPB + threadIdx.x;   // sample index, exact fit

    // 5 independent LDG.64 (MLP = 5), issued first.
    float2 v[5];
    const float2* src = inputs2 + t * 5;
    #pragma unroll
    for (int i = 0; i < 5; i++) v[i] = src[i];

    // Vectorized uniform broadcast loads of the parameter vectors.
    float r[N_QUBITS];
    {
        float4 r0 = __ldg(reinterpret_cast<const float4*>(rot));      // rot[0..3]
        float4 r1 = __ldg(reinterpret_cast<const float4*>(rot) + 1);  // rot[4..7]
        float2 r2 = __ldg(reinterpret_cast<const float2*>(rot) + 4);  // rot[8..9]
        r[0] = r0.x; r[1] = r0.y; r[2] = r0.z; r[3] = r0.w;
        r[4] = r1.x; r[5] = r1.y; r[6] = r1.z; r[7] = r1.w;
        r[8] = r2.x; r[9] = r2.y;
    }
    float ev_raw[N_QUBITS - 1];
    {
        float4 e0 = __ldg(reinterpret_cast<const float4*>(ent));      // ent[0..3]
        float4 e1 = __ldg(reinterpret_cast<const float4*>(ent) + 1);  // ent[4..7]
        float  e2 = __ldg(ent + 8);                                   // ent[8]
        ev_raw[0] = e0.x; ev_raw[1] = e0.y; ev_raw[2] = e0.z; ev_raw[3] = e0.w;
        ev_raw[4] = e1.x; ev_raw[5] = e1.y; ev_raw[6] = e1.z; ev_raw[7] = e1.w;
        ev_raw[8] = e2;
    }
    float k[N_QUBITS - 1], kc[N_QUBITS - 1];
    #pragma unroll
    for (int i = 0; i < N_QUBITS - 1; i++) {
        float ce = __cosf(ev_raw[i]);
        k[i]  = __fmaf_rn(-0.5f, ce, 0.5f);   // sin^2(e/2) = (1 - cos e)/2
        kc[i] = __fmaf_rn( 0.5f, ce, 0.5f);   // 1 - k      = (1 + cos e)/2
    }

    float x[N_QUBITS];
    #pragma unroll
    for (int i = 0; i < 5; i++) { x[2*i] = v[i].x; x[2*i+1] = v[i].y; }

    // All 10 cos are independent (pipelined MUFU); carry chain is
    // mul + fma per step (the minimal 2-op serial form).
    float c[N_QUBITS];
    #pragma unroll
    for (int i = 0; i < N_QUBITS; i++) c[i] = __cosf(x[i] + r[i]);

    float e[N_QUBITS];
    float carry = 1.0f;
    #pragma unroll
    for (int i = 0; i < N_QUBITS; i++) {
        float ev = c[i] * carry;
        e[i] = ev;
        if (i < N_QUBITS - 1) carry = __fmaf_rn(k[i], ev, kc[i]);
    }

    float2* dst = out2 + t * 5;
    #pragma unroll
    for (int i = 0; i < 5; i++) {
        float2 o; o.x = e[2*i]; o.y = e[2*i+1];
        dst[i] = o;
    }
}

extern "C" void kernel_launch(void* const* d_in, const int* in_sizes, int n_in,
                              void* d_out, int out_size) {
    const float* inputs = (const float*)d_in[0];  // (16, 1024, 10) fp32
    const float* rot    = (const float*)d_in[1];  // (10,)
    const float* ent    = (const float*)d_in[2];  // (9,)
    float* out = (float*)d_out;

    int total_elems = in_sizes[0];                 // 163840
    int T = total_elems / N_QUBITS;                // 16384 samples
    int blocks = T / TPB;                          // 128, exact

    qsa_closed_form_kernel<<<blocks, TPB>>>(
        reinterpret_cast<const float2*>(inputs), rot, ent,
        reinterpret_cast<float2*>(out));
}